// round 13
// baseline (speedup 1.0000x reference)
#include <cuda_runtime.h>
#include <cuda_bf16.h>

#define B 32768
#define C 1000
#define NV4 250            // float4 per row
#define NBLK 4096          // 8 rows/block, 1 row/warp, wave-based

// INVARIANTS at kernel_launch entry (zero at module load, restored by finisher):
//   g_cnt == 0, g_done == 0.
__device__ int      g_cnt[C];
__device__ float    g_row[B];
__device__ unsigned g_done;

// Finisher in a separate ABI-called function so its code cannot perturb the
// engine's register allocation / front-batched load scheduling (the R10 bug).
__device__ __noinline__ void finisher(const int* __restrict__ label,
                                      float*     __restrict__ out)
{
    __shared__ int   scnt[C];
    __shared__ float swarp[8];
    const int tid  = threadIdx.x;
    const int lane = tid & 31;
    const int wid  = tid >> 5;

    // stage g_cnt in smem (coalesced), then gather per-row from smem
    #pragma unroll
    for (int k = 0; k < 4; k++) {
        int c = tid + 256 * k;
        if (c < C) scnt[c] = g_cnt[c];
    }
    __syncthreads();

    float s = 0.f;
    #pragma unroll 4
    for (int i = tid; i < B / 4; i += 256) {
        float4 v = __ldcg((const float4*)g_row + i);
        int4   L = ((const int4*)label)[i];
        s += __fdividef(v.x, (float)max(scnt[min(max(L.x, 0), C - 1)], 1));
        s += __fdividef(v.y, (float)max(scnt[min(max(L.y, 0), C - 1)], 1));
        s += __fdividef(v.z, (float)max(scnt[min(max(L.z, 0), C - 1)], 1));
        s += __fdividef(v.w, (float)max(scnt[min(max(L.w, 0), C - 1)], 1));
    }
    #pragma unroll
    for (int o = 16; o; o >>= 1) s += __shfl_xor_sync(0xFFFFFFFFu, s, o);
    if (lane == 0) swarp[wid] = s;
    __syncthreads();
    if (tid == 0) {
        float r = 0.f;
        #pragma unroll
        for (int k = 0; k < 8; k++) r += swarp[k];
        out[0] = r * (1.0f / (float)C);
    }
    // restore invariants for next call / graph replay
    __syncthreads();
    for (int k = tid; k < C; k += 256) g_cnt[k] = 0;
    if (tid == 0) g_done = 0u;
}

__global__ __launch_bounds__(256) void kl_all_kernel(
    const float* __restrict__ f1,
    const float* __restrict__ f2,
    const int*   __restrict__ label,
    float*       __restrict__ out)
{
    __shared__ int s_last;
    const int tid  = threadIdx.x;
    const int lane = tid & 31;
    const int wid  = tid >> 5;

    // hist prologue: blocks 0..31 cover all 32768 labels (int4 loads).
    // g_cnt has no reader until the finisher, so this overlaps with streaming.
    if (blockIdx.x < 32) {
        int i = blockIdx.x * 256 + tid;
        int4 L = ((const int4*)label)[i];
        atomicAdd(&g_cnt[min(max(L.x, 0), C - 1)], 1);
        atomicAdd(&g_cnt[min(max(L.y, 0), C - 1)], 1);
        atomicAdd(&g_cnt[min(max(L.z, 0), C - 1)], 1);
        atomicAdd(&g_cnt[min(max(L.w, 0), C - 1)], 1);
    }

    // ---- engine (identical to R11): one row per warp, front-batched loads ----
    const int row = blockIdx.x * 8 + wid;
    const float4* p1 = (const float4*)f1 + (size_t)row * NV4;
    const float4* p2 = (const float4*)f2 + (size_t)row * NV4;

    float4 a[8], b[8];
    const float4 NEG = make_float4(-1e30f, -1e30f, -1e30f, -1e30f);
    #pragma unroll
    for (int k = 0; k < 8; k++) {
        int j = lane + 32 * k;
        if (j < NV4) { a[k] = p1[j]; b[k] = p2[j]; }
        else         { a[k] = NEG;   b[k] = NEG;   }
    }

    // pass 1: row maxes (consumes whole row -> ptxas front-batches all loads)
    float m1 = -1e30f, m2 = -1e30f;
    #pragma unroll
    for (int k = 0; k < 8; k++) {
        m1 = fmaxf(m1, fmaxf(fmaxf(a[k].x, a[k].y), fmaxf(a[k].z, a[k].w)));
        m2 = fmaxf(m2, fmaxf(fmaxf(b[k].x, b[k].y), fmaxf(b[k].z, b[k].w)));
    }
    #pragma unroll
    for (int o = 16; o; o >>= 1) {
        m1 = fmaxf(m1, __shfl_xor_sync(0xFFFFFFFFu, m1, o));
        m2 = fmaxf(m2, __shfl_xor_sync(0xFFFFFFFFu, m2, o));
    }

    // pass 2 (registers): s1, s2, wv
    float s1 = 0.f, s2 = 0.f, wv = 0.f;
    #pragma unroll
    for (int k = 0; k < 8; k++) {
        s1 += __expf(a[k].x - m1) + __expf(a[k].y - m1)
            + __expf(a[k].z - m1) + __expf(a[k].w - m1);
        float e;
        e = __expf(b[k].x - m2); s2 += e; wv = fmaf(e, b[k].x - a[k].x, wv);
        e = __expf(b[k].y - m2); s2 += e; wv = fmaf(e, b[k].y - a[k].y, wv);
        e = __expf(b[k].z - m2); s2 += e; wv = fmaf(e, b[k].z - a[k].z, wv);
        e = __expf(b[k].w - m2); s2 += e; wv = fmaf(e, b[k].w - a[k].w, wv);
    }
    #pragma unroll
    for (int o = 16; o; o >>= 1) {
        s1 += __shfl_xor_sync(0xFFFFFFFFu, s1, o);
        s2 += __shfl_xor_sync(0xFFFFFFFFu, s2, o);
        wv += __shfl_xor_sync(0xFFFFFFFFu, wv, o);
    }

    if (lane == 0) {
        g_row[row] = wv / s2 + (m1 + __logf(s1)) - (m2 + __logf(s2));
        __threadfence();   // release: writer-side fence before ticket arrive
    }

    // ---- ticket: last block becomes the finisher ----
    __syncthreads();
    if (tid == 0) {
        unsigned old = atomicAdd(&g_done, 1u);
        s_last = (old == (unsigned)(NBLK - 1)) ? 1 : 0;
        if (s_last) __threadfence();   // acquire: order subsequent reads
    }
    __syncthreads();
    if (s_last) finisher(label, out);
}

extern "C" void kernel_launch(void* const* d_in, const int* in_sizes, int n_in,
                              void* d_out, int out_size)
{
    const float* f1    = (const float*)d_in[0];
    const float* f2    = (const float*)d_in[1];
    const int*   label = (const int*)d_in[2];
    float*       out   = (float*)d_out;

    kl_all_kernel<<<NBLK, 256>>>(f1, f2, label, out);
}